// round 7
// baseline (speedup 1.0000x reference)
#include <cuda_runtime.h>
#include <cuda_bf16.h>
#include <cstdint>

// VectorQuantizer: x[131072,64] f32, W[1024,64] f32.
// out = [quantized(N,64) | quantized(N,64) | indices-as-f32(N)]
// argmin_k ||f-w_k||^2 == argmax_k ( f.w_k - 0.5||w_k||^2 )
// mma.sync bf16, exact 3-way split, 6 product passes (hh,hm,mh,hl,lh,mm).
// R6: paired-ntile MMA scheduling (dep distance 2 -> 4) to close tensor idle.

#define NROWS   131072
#define DIM     64
#define NCODE   1024
#define MCTA    128
#define NCHUNK  64
#define NCHUNKS (NCODE / NCHUNK)
#define THREADS 256

#define ROWB    144                     // padded row stride (72 bf16)
#define SPLIT_A (MCTA * ROWB)           // 18432
#define SPLIT_B (NCHUNK * ROWB)         // 9216
#define BUF_B   (3 * SPLIT_B)           // 27648
#define SM_A    0
#define SM_B    (3 * SPLIT_A)           // 55296
#define SM_BIAS (SM_B + 2 * BUF_B)      // 110592
#define SMEM_TOTAL (SM_BIAS + 512)      // 111104

__device__ __align__(16) __nv_bfloat16 g_Wsplit[3][NCODE][DIM];
__device__ __align__(16) float g_bias[NCODE];

// ---- helpers ---------------------------------------------------------------
__device__ __forceinline__ uint32_t smem_to_u32(const void* p) {
    uint32_t a;
    asm("{ .reg .u64 t; cvta.to.shared.u64 t, %1; cvt.u32.u64 %0, t; }" : "=r"(a) : "l"(p));
    return a;
}
__device__ __forceinline__ void split3(float v, __nv_bfloat16& h, __nv_bfloat16& m, __nv_bfloat16& l) {
    h = __float2bfloat16_rn(v);
    float r1 = v - __bfloat162float(h);
    m = __float2bfloat16_rn(r1);
    float r2 = r1 - __bfloat162float(m);
    l = __float2bfloat16_rn(r2);
}
__device__ __forceinline__ uint32_t pack2(__nv_bfloat16 a, __nv_bfloat16 b) {
    __nv_bfloat162 t = __halves2bfloat162(a, b);
    return *reinterpret_cast<uint32_t*>(&t);
}
#define LDSM_X4(r0, r1, r2, r3, a) \
    asm volatile("ldmatrix.sync.aligned.m8n8.x4.shared.b16 {%0,%1,%2,%3}, [%4];" \
                 : "=r"(r0), "=r"(r1), "=r"(r2), "=r"(r3) : "r"(a))
#define MMA_BF16(d, a, b) \
    asm volatile("mma.sync.aligned.m16n8k16.row.col.f32.bf16.bf16.f32 " \
                 "{%0,%1,%2,%3}, {%4,%5,%6,%7}, {%8,%9}, {%0,%1,%2,%3};" \
                 : "+f"((d)[0]), "+f"((d)[1]), "+f"((d)[2]), "+f"((d)[3]) \
                 : "r"((a)[0]), "r"((a)[1]), "r"((a)[2]), "r"((a)[3]), "r"((b)[0]), "r"((b)[1]))
#define CP_ASYNC16(dst, src) \
    asm volatile("cp.async.cg.shared.global [%0], [%1], 16;" \
                 :: "r"((uint32_t)(dst)), "l"((size_t)__cvta_generic_to_global(src)) : "memory")
#define CP_COMMIT() asm volatile("cp.async.commit_group;" ::: "memory")
#define CP_WAIT(n)  asm volatile("cp.async.wait_group %0;" :: "n"(n) : "memory")

// ---- prep: split codebook + bias -------------------------------------------
__global__ void prep_kernel(const float* __restrict__ W) {
    int k = blockIdx.x * blockDim.x + threadIdx.x;
    if (k >= NCODE) return;
    float s = 0.0f;
#pragma unroll
    for (int d = 0; d < DIM; d++) {
        float v = W[(size_t)k * DIM + d];
        __nv_bfloat16 h, m, l;
        split3(v, h, m, l);
        g_Wsplit[0][k][d] = h; g_Wsplit[1][k][d] = m; g_Wsplit[2][k][d] = l;
        s = fmaf(v, v, s);
    }
    g_bias[k] = -0.5f * s;
}

// issue cp.async for B chunk `kbase` into buffer bsel
__device__ __forceinline__ void prefetch_chunk(uint32_t sbase, int bsel, int kbase, int tid) {
    const char* gw = reinterpret_cast<const char*>(g_Wsplit);
#pragma unroll
    for (int t = 0; t < 6; t++) {
        int i = tid + t * THREADS;                 // 0..1535
        int split = i >> 9, rem = i & 511, n = rem >> 3, ch = rem & 7;
        uint32_t dst = sbase + SM_B + bsel * BUF_B + split * SPLIT_B + n * ROWB + ch * 16;
        const char* src = gw + (((size_t)split * NCODE + kbase + n) * 8 + ch) * 16;
        CP_ASYNC16(dst, src);
    }
    if (tid < 16)
        CP_ASYNC16(sbase + SM_BIAS + bsel * 256 + tid * 16,
                   reinterpret_cast<const char*>(g_bias) + (size_t)kbase * 4 + tid * 16);
    CP_COMMIT();
}

// ---- main kernel ------------------------------------------------------------
__global__ __launch_bounds__(THREADS, 2)
void vq_kernel(const float* __restrict__ x,
               const float* __restrict__ W,
               float* __restrict__ out) {
    extern __shared__ char smem[];
    const uint32_t sbase = smem_to_u32(smem);
    const int tid  = threadIdx.x;
    const int lane = tid & 31;
    const int wid  = tid >> 5;
    const int wm   = wid * 16;          // 16 rows per warp, all 64 codes/chunk

    // kick off chunk 0 load before anything else
    prefetch_chunk(sbase, 0, 0, tid);

    // ---- stage A rows into smem (3-way split) -------------
    {
        const int row = tid >> 1, half = tid & 1;
        const float4* xr = reinterpret_cast<const float4*>(
            x + ((size_t)blockIdx.x * MCTA + row) * DIM + half * 32);
        char* a0 = smem + SM_A + row * ROWB + half * 64;
#pragma unroll
        for (int i = 0; i < 8; i++) {
            float4 v = xr[i];
            __nv_bfloat16 h0, m0, l0, h1, m1, l1, h2, m2, l2, h3, m3, l3;
            split3(v.x, h0, m0, l0); split3(v.y, h1, m1, l1);
            split3(v.z, h2, m2, l2); split3(v.w, h3, m3, l3);
            *reinterpret_cast<uint32_t*>(a0 + 0 * SPLIT_A + i * 8)     = pack2(h0, h1);
            *reinterpret_cast<uint32_t*>(a0 + 0 * SPLIT_A + i * 8 + 4) = pack2(h2, h3);
            *reinterpret_cast<uint32_t*>(a0 + 1 * SPLIT_A + i * 8)     = pack2(m0, m1);
            *reinterpret_cast<uint32_t*>(a0 + 1 * SPLIT_A + i * 8 + 4) = pack2(m2, m3);
            *reinterpret_cast<uint32_t*>(a0 + 2 * SPLIT_A + i * 8)     = pack2(l0, l1);
            *reinterpret_cast<uint32_t*>(a0 + 2 * SPLIT_A + i * 8 + 4) = pack2(l2, l3);
        }
    }
    __syncthreads();

    // ---- A fragments -> registers, persistent for all chunks ----
    uint32_t Af[3][4][4];
    {
        const uint32_t aB = sbase + SM_A + (uint32_t)(wm + (lane & 15)) * ROWB + (lane >> 4) * 16;
#pragma unroll
        for (int sa = 0; sa < 3; sa++)
#pragma unroll
            for (int k = 0; k < 4; k++)
                LDSM_X4(Af[sa][k][0], Af[sa][k][1], Af[sa][k][2], Af[sa][k][3],
                        aB + sa * SPLIT_A + k * 32);
    }

    float best[2] = {-3.0e38f, -3.0e38f};
    int   bidx[2] = {0, 0};

    // B ldmatrix base: x4 covers two n-tiles (codes n0..n0+7 and n0+8..n0+15)
    const uint32_t bb = sbase + SM_B
        + (uint32_t)(((lane >> 4) & 1) * 8 + (lane & 7)) * ROWB
        + ((lane >> 3) & 1) * 16;

    for (int c = 0; c < NCHUNKS; c++) {
        if (c + 1 < NCHUNKS) {
            prefetch_chunk(sbase, (c + 1) & 1, (c + 1) * NCHUNK, tid);
            CP_WAIT(1);
        } else {
            CP_WAIT(0);
        }
        __syncthreads();

        const float* sBias = reinterpret_cast<const float*>(smem + SM_BIAS + (c & 1) * 256);
        float acc[8][4];
#pragma unroll
        for (int nt = 0; nt < 8; nt++) {
            float2 b01 = *reinterpret_cast<const float2*>(&sBias[nt * 8 + (lane & 3) * 2]);
            acc[nt][0] = b01.x; acc[nt][1] = b01.y;
            acc[nt][2] = b01.x; acc[nt][3] = b01.y;
        }

        const uint32_t bbc = bb + (c & 1) * BUF_B;
#pragma unroll
        for (int k = 0; k < 4; k++) {
#pragma unroll
            for (int sb = 0; sb < 3; sb++) {
#pragma unroll
                for (int np = 0; np < 2; np++) {   // pairs of 16-wide n-tiles
                    uint32_t Bf0[4], Bf1[4];
                    uint32_t bB = bbc + sb * SPLIT_B + np * 32 * ROWB + k * 32;
                    LDSM_X4(Bf0[0], Bf0[1], Bf0[2], Bf0[3], bB);
                    LDSM_X4(Bf1[0], Bf1[1], Bf1[2], Bf1[3], bB + 16 * ROWB);
                    // 4 independent acc chains per sa step (dep distance 4)
#pragma unroll
                    for (int sa = 0; sa < 3 - sb; sa++) {
                        MMA_BF16(acc[4 * np + 0], Af[sa][k], Bf0);
                        MMA_BF16(acc[4 * np + 1], Af[sa][k], Bf0 + 2);
                        MMA_BF16(acc[4 * np + 2], Af[sa][k], Bf1);
                        MMA_BF16(acc[4 * np + 3], Af[sa][k], Bf1 + 2);
                    }
                }
            }
        }

        // argmax update: 2 row-chains per thread (rows lane>>2 and +8)
#pragma unroll
        for (int nt = 0; nt < 8; nt++)
#pragma unroll
            for (int q = 0; q < 2; q++)
#pragma unroll
                for (int e = 0; e < 2; e++) {
                    float v = acc[nt][q * 2 + e];
                    int n = c * NCHUNK + nt * 8 + (lane & 3) * 2 + e;
                    if (v > best[q]) { best[q] = v; bidx[q] = n; }
                }

        __syncthreads();   // buf (c&1) free for the c+2 prefetch
    }

    // ---- reduce across the 4 lanes sharing each row (cols) ----
#pragma unroll
    for (int q = 0; q < 2; q++) {
#pragma unroll
        for (int off = 1; off < 4; off <<= 1) {
            float ov = __shfl_xor_sync(0xFFFFFFFFu, best[q], off);
            int   oi = __shfl_xor_sync(0xFFFFFFFFu, bidx[q], off);
            if (ov > best[q] || (ov == best[q] && oi < bidx[q])) {
                best[q] = ov; bidx[q] = oi;
            }
        }
    }

    // ---- gather codewords + write outputs ----
    const int lq = lane & 3;   // dim slice lq*16 .. lq*16+15
#pragma unroll
    for (int q = 0; q < 2; q++) {
        const int r = wm + (lane >> 2) + q * 8;
        const size_t grow = (size_t)blockIdx.x * MCTA + r;
        const int K = bidx[q];
        const float4* wsrc = reinterpret_cast<const float4*>(W + (size_t)K * DIM + lq * 16);
        float4* o1 = reinterpret_cast<float4*>(out + grow * DIM + lq * 16);
        float4* o2 = reinterpret_cast<float4*>(out + ((size_t)NROWS + grow) * DIM + lq * 16);
#pragma unroll
        for (int i = 0; i < 4; i++) {
            float4 v = wsrc[i];
            o1[i] = v;
            o2[i] = v;
        }
        if (lq == 0)
            out[(size_t)2 * NROWS * DIM + grow] = (float)K;
    }
}

// ---- launch -----------------------------------------------------------------
extern "C" void kernel_launch(void* const* d_in, const int* in_sizes, int n_in,
                              void* d_out, int out_size) {
    const float* x = (const float*)d_in[0];
    const float* W = (const float*)d_in[1];
    float* out = (float*)d_out;

    cudaFuncSetAttribute(vq_kernel, cudaFuncAttributeMaxDynamicSharedMemorySize, SMEM_TOTAL);
    prep_kernel<<<NCODE / 256, 256>>>(W);
    vq_kernel<<<NROWS / MCTA, THREADS, SMEM_TOTAL>>>(x, W, out);
}

// round 8
// speedup vs baseline: 1.0029x; 1.0029x over previous
#include <cuda_runtime.h>
#include <cuda_bf16.h>
#include <cstdint>

// VectorQuantizer: x[131072,64] f32, W[1024,64] f32.
// out = [quantized(N,64) | quantized(N,64) | indices-as-f32(N)]
// argmin_k ||f-w_k||^2 == argmax_k ( f.w_k - 0.5||w_k||^2 )
// mma.sync bf16, exact 3-way split, 6 product passes (hh,hm,mh,hl,lh,mm).
// R6: paired-ntile MMA scheduling (dep distance 2 -> 4) to close tensor idle.

#define NROWS   131072
#define DIM     64
#define NCODE   1024
#define MCTA    128
#define NCHUNK  64
#define NCHUNKS (NCODE / NCHUNK)
#define THREADS 256

#define ROWB    144                     // padded row stride (72 bf16)
#define SPLIT_A (MCTA * ROWB)           // 18432
#define SPLIT_B (NCHUNK * ROWB)         // 9216
#define BUF_B   (3 * SPLIT_B)           // 27648
#define SM_A    0
#define SM_B    (3 * SPLIT_A)           // 55296
#define SM_BIAS (SM_B + 2 * BUF_B)      // 110592
#define SMEM_TOTAL (SM_BIAS + 512)      // 111104

__device__ __align__(16) __nv_bfloat16 g_Wsplit[3][NCODE][DIM];
__device__ __align__(16) float g_bias[NCODE];

// ---- helpers ---------------------------------------------------------------
__device__ __forceinline__ uint32_t smem_to_u32(const void* p) {
    uint32_t a;
    asm("{ .reg .u64 t; cvta.to.shared.u64 t, %1; cvt.u32.u64 %0, t; }" : "=r"(a) : "l"(p));
    return a;
}
__device__ __forceinline__ void split3(float v, __nv_bfloat16& h, __nv_bfloat16& m, __nv_bfloat16& l) {
    h = __float2bfloat16_rn(v);
    float r1 = v - __bfloat162float(h);
    m = __float2bfloat16_rn(r1);
    float r2 = r1 - __bfloat162float(m);
    l = __float2bfloat16_rn(r2);
}
__device__ __forceinline__ uint32_t pack2(__nv_bfloat16 a, __nv_bfloat16 b) {
    __nv_bfloat162 t = __halves2bfloat162(a, b);
    return *reinterpret_cast<uint32_t*>(&t);
}
#define LDSM_X4(r0, r1, r2, r3, a) \
    asm volatile("ldmatrix.sync.aligned.m8n8.x4.shared.b16 {%0,%1,%2,%3}, [%4];" \
                 : "=r"(r0), "=r"(r1), "=r"(r2), "=r"(r3) : "r"(a))
#define MMA_BF16(d, a, b) \
    asm volatile("mma.sync.aligned.m16n8k16.row.col.f32.bf16.bf16.f32 " \
                 "{%0,%1,%2,%3}, {%4,%5,%6,%7}, {%8,%9}, {%0,%1,%2,%3};" \
                 : "+f"((d)[0]), "+f"((d)[1]), "+f"((d)[2]), "+f"((d)[3]) \
                 : "r"((a)[0]), "r"((a)[1]), "r"((a)[2]), "r"((a)[3]), "r"((b)[0]), "r"((b)[1]))
#define CP_ASYNC16(dst, src) \
    asm volatile("cp.async.cg.shared.global [%0], [%1], 16;" \
                 :: "r"((uint32_t)(dst)), "l"((size_t)__cvta_generic_to_global(src)) : "memory")
#define CP_COMMIT() asm volatile("cp.async.commit_group;" ::: "memory")
#define CP_WAIT(n)  asm volatile("cp.async.wait_group %0;" :: "n"(n) : "memory")

// ---- prep: split codebook + bias -------------------------------------------
__global__ void prep_kernel(const float* __restrict__ W) {
    int k = blockIdx.x * blockDim.x + threadIdx.x;
    if (k >= NCODE) return;
    float s = 0.0f;
#pragma unroll
    for (int d = 0; d < DIM; d++) {
        float v = W[(size_t)k * DIM + d];
        __nv_bfloat16 h, m, l;
        split3(v, h, m, l);
        g_Wsplit[0][k][d] = h; g_Wsplit[1][k][d] = m; g_Wsplit[2][k][d] = l;
        s = fmaf(v, v, s);
    }
    g_bias[k] = -0.5f * s;
}

// issue cp.async for B chunk `kbase` into buffer bsel
__device__ __forceinline__ void prefetch_chunk(uint32_t sbase, int bsel, int kbase, int tid) {
    const char* gw = reinterpret_cast<const char*>(g_Wsplit);
#pragma unroll
    for (int t = 0; t < 6; t++) {
        int i = tid + t * THREADS;                 // 0..1535
        int split = i >> 9, rem = i & 511, n = rem >> 3, ch = rem & 7;
        uint32_t dst = sbase + SM_B + bsel * BUF_B + split * SPLIT_B + n * ROWB + ch * 16;
        const char* src = gw + (((size_t)split * NCODE + kbase + n) * 8 + ch) * 16;
        CP_ASYNC16(dst, src);
    }
    if (tid < 16)
        CP_ASYNC16(sbase + SM_BIAS + bsel * 256 + tid * 16,
                   reinterpret_cast<const char*>(g_bias) + (size_t)kbase * 4 + tid * 16);
    CP_COMMIT();
}

// ---- main kernel ------------------------------------------------------------
__global__ __launch_bounds__(THREADS, 2)
void vq_kernel(const float* __restrict__ x,
               const float* __restrict__ W,
               float* __restrict__ out) {
    extern __shared__ char smem[];
    const uint32_t sbase = smem_to_u32(smem);
    const int tid  = threadIdx.x;
    const int lane = tid & 31;
    const int wid  = tid >> 5;
    const int wm   = wid * 16;          // 16 rows per warp, all 64 codes/chunk

    // kick off chunk 0 load before anything else
    prefetch_chunk(sbase, 0, 0, tid);

    // ---- stage A rows into smem (3-way split) -------------
    {
        const int row = tid >> 1, half = tid & 1;
        const float4* xr = reinterpret_cast<const float4*>(
            x + ((size_t)blockIdx.x * MCTA + row) * DIM + half * 32);
        char* a0 = smem + SM_A + row * ROWB + half * 64;
#pragma unroll
        for (int i = 0; i < 8; i++) {
            float4 v = xr[i];
            __nv_bfloat16 h0, m0, l0, h1, m1, l1, h2, m2, l2, h3, m3, l3;
            split3(v.x, h0, m0, l0); split3(v.y, h1, m1, l1);
            split3(v.z, h2, m2, l2); split3(v.w, h3, m3, l3);
            *reinterpret_cast<uint32_t*>(a0 + 0 * SPLIT_A + i * 8)     = pack2(h0, h1);
            *reinterpret_cast<uint32_t*>(a0 + 0 * SPLIT_A + i * 8 + 4) = pack2(h2, h3);
            *reinterpret_cast<uint32_t*>(a0 + 1 * SPLIT_A + i * 8)     = pack2(m0, m1);
            *reinterpret_cast<uint32_t*>(a0 + 1 * SPLIT_A + i * 8 + 4) = pack2(m2, m3);
            *reinterpret_cast<uint32_t*>(a0 + 2 * SPLIT_A + i * 8)     = pack2(l0, l1);
            *reinterpret_cast<uint32_t*>(a0 + 2 * SPLIT_A + i * 8 + 4) = pack2(l2, l3);
        }
    }
    __syncthreads();

    // ---- A fragments -> registers, persistent for all chunks ----
    uint32_t Af[3][4][4];
    {
        const uint32_t aB = sbase + SM_A + (uint32_t)(wm + (lane & 15)) * ROWB + (lane >> 4) * 16;
#pragma unroll
        for (int sa = 0; sa < 3; sa++)
#pragma unroll
            for (int k = 0; k < 4; k++)
                LDSM_X4(Af[sa][k][0], Af[sa][k][1], Af[sa][k][2], Af[sa][k][3],
                        aB + sa * SPLIT_A + k * 32);
    }

    float best[2] = {-3.0e38f, -3.0e38f};
    int   bidx[2] = {0, 0};

    // B ldmatrix base: x4 covers two n-tiles (codes n0..n0+7 and n0+8..n0+15)
    const uint32_t bb = sbase + SM_B
        + (uint32_t)(((lane >> 4) & 1) * 8 + (lane & 7)) * ROWB
        + ((lane >> 3) & 1) * 16;

    for (int c = 0; c < NCHUNKS; c++) {
        if (c + 1 < NCHUNKS) {
            prefetch_chunk(sbase, (c + 1) & 1, (c + 1) * NCHUNK, tid);
            CP_WAIT(1);
        } else {
            CP_WAIT(0);
        }
        __syncthreads();

        const float* sBias = reinterpret_cast<const float*>(smem + SM_BIAS + (c & 1) * 256);
        float acc[8][4];
#pragma unroll
        for (int nt = 0; nt < 8; nt++) {
            float2 b01 = *reinterpret_cast<const float2*>(&sBias[nt * 8 + (lane & 3) * 2]);
            acc[nt][0] = b01.x; acc[nt][1] = b01.y;
            acc[nt][2] = b01.x; acc[nt][3] = b01.y;
        }

        const uint32_t bbc = bb + (c & 1) * BUF_B;
#pragma unroll
        for (int k = 0; k < 4; k++) {
#pragma unroll
            for (int sb = 0; sb < 3; sb++) {
#pragma unroll
                for (int np = 0; np < 2; np++) {   // pairs of 16-wide n-tiles
                    uint32_t Bf0[4], Bf1[4];
                    uint32_t bB = bbc + sb * SPLIT_B + np * 32 * ROWB + k * 32;
                    LDSM_X4(Bf0[0], Bf0[1], Bf0[2], Bf0[3], bB);
                    LDSM_X4(Bf1[0], Bf1[1], Bf1[2], Bf1[3], bB + 16 * ROWB);
                    // 4 independent acc chains per sa step (dep distance 4)
#pragma unroll
                    for (int sa = 0; sa < 3 - sb; sa++) {
                        MMA_BF16(acc[4 * np + 0], Af[sa][k], Bf0);
                        MMA_BF16(acc[4 * np + 1], Af[sa][k], Bf0 + 2);
                        MMA_BF16(acc[4 * np + 2], Af[sa][k], Bf1);
                        MMA_BF16(acc[4 * np + 3], Af[sa][k], Bf1 + 2);
                    }
                }
            }
        }

        // argmax update: 2 row-chains per thread (rows lane>>2 and +8)
#pragma unroll
        for (int nt = 0; nt < 8; nt++)
#pragma unroll
            for (int q = 0; q < 2; q++)
#pragma unroll
                for (int e = 0; e < 2; e++) {
                    float v = acc[nt][q * 2 + e];
                    int n = c * NCHUNK + nt * 8 + (lane & 3) * 2 + e;
                    if (v > best[q]) { best[q] = v; bidx[q] = n; }
                }

        __syncthreads();   // buf (c&1) free for the c+2 prefetch
    }

    // ---- reduce across the 4 lanes sharing each row (cols) ----
#pragma unroll
    for (int q = 0; q < 2; q++) {
#pragma unroll
        for (int off = 1; off < 4; off <<= 1) {
            float ov = __shfl_xor_sync(0xFFFFFFFFu, best[q], off);
            int   oi = __shfl_xor_sync(0xFFFFFFFFu, bidx[q], off);
            if (ov > best[q] || (ov == best[q] && oi < bidx[q])) {
                best[q] = ov; bidx[q] = oi;
            }
        }
    }

    // ---- gather codewords + write outputs ----
    const int lq = lane & 3;   // dim slice lq*16 .. lq*16+15
#pragma unroll
    for (int q = 0; q < 2; q++) {
        const int r = wm + (lane >> 2) + q * 8;
        const size_t grow = (size_t)blockIdx.x * MCTA + r;
        const int K = bidx[q];
        const float4* wsrc = reinterpret_cast<const float4*>(W + (size_t)K * DIM + lq * 16);
        float4* o1 = reinterpret_cast<float4*>(out + grow * DIM + lq * 16);
        float4* o2 = reinterpret_cast<float4*>(out + ((size_t)NROWS + grow) * DIM + lq * 16);
#pragma unroll
        for (int i = 0; i < 4; i++) {
            float4 v = wsrc[i];
            o1[i] = v;
            o2[i] = v;
        }
        if (lq == 0)
            out[(size_t)2 * NROWS * DIM + grow] = (float)K;
    }
}

// ---- launch -----------------------------------------------------------------
extern "C" void kernel_launch(void* const* d_in, const int* in_sizes, int n_in,
                              void* d_out, int out_size) {
    const float* x = (const float*)d_in[0];
    const float* W = (const float*)d_in[1];
    float* out = (float*)d_out;

    cudaFuncSetAttribute(vq_kernel, cudaFuncAttributeMaxDynamicSharedMemorySize, SMEM_TOTAL);
    prep_kernel<<<NCODE / 256, 256>>>(W);
    vq_kernel<<<NROWS / MCTA, THREADS, SMEM_TOTAL>>>(x, W, out);
}

// round 9
// speedup vs baseline: 1.0041x; 1.0011x over previous
#include <cuda_runtime.h>
#include <cuda_bf16.h>
#include <cstdint>

// VectorQuantizer: x[131072,64] f32, W[1024,64] f32.
// out = [quantized(N,64) | quantized(N,64) | indices-as-f32(N)]
// argmin_k ||f-w_k||^2 == argmax_k ( f.w_k - 0.5||w_k||^2 )
// mma.sync bf16, exact 3-way split, 6 product passes (hh,hm,mh,hl,lh,mm).
// R6: paired-ntile MMA scheduling (dep distance 2 -> 4) to close tensor idle.

#define NROWS   131072
#define DIM     64
#define NCODE   1024
#define MCTA    128
#define NCHUNK  64
#define NCHUNKS (NCODE / NCHUNK)
#define THREADS 256

#define ROWB    144                     // padded row stride (72 bf16)
#define SPLIT_A (MCTA * ROWB)           // 18432
#define SPLIT_B (NCHUNK * ROWB)         // 9216
#define BUF_B   (3 * SPLIT_B)           // 27648
#define SM_A    0
#define SM_B    (3 * SPLIT_A)           // 55296
#define SM_BIAS (SM_B + 2 * BUF_B)      // 110592
#define SMEM_TOTAL (SM_BIAS + 512)      // 111104

__device__ __align__(16) __nv_bfloat16 g_Wsplit[3][NCODE][DIM];
__device__ __align__(16) float g_bias[NCODE];

// ---- helpers ---------------------------------------------------------------
__device__ __forceinline__ uint32_t smem_to_u32(const void* p) {
    uint32_t a;
    asm("{ .reg .u64 t; cvta.to.shared.u64 t, %1; cvt.u32.u64 %0, t; }" : "=r"(a) : "l"(p));
    return a;
}
__device__ __forceinline__ void split3(float v, __nv_bfloat16& h, __nv_bfloat16& m, __nv_bfloat16& l) {
    h = __float2bfloat16_rn(v);
    float r1 = v - __bfloat162float(h);
    m = __float2bfloat16_rn(r1);
    float r2 = r1 - __bfloat162float(m);
    l = __float2bfloat16_rn(r2);
}
__device__ __forceinline__ uint32_t pack2(__nv_bfloat16 a, __nv_bfloat16 b) {
    __nv_bfloat162 t = __halves2bfloat162(a, b);
    return *reinterpret_cast<uint32_t*>(&t);
}
#define LDSM_X4(r0, r1, r2, r3, a) \
    asm volatile("ldmatrix.sync.aligned.m8n8.x4.shared.b16 {%0,%1,%2,%3}, [%4];" \
                 : "=r"(r0), "=r"(r1), "=r"(r2), "=r"(r3) : "r"(a))
#define MMA_BF16(d, a, b) \
    asm volatile("mma.sync.aligned.m16n8k16.row.col.f32.bf16.bf16.f32 " \
                 "{%0,%1,%2,%3}, {%4,%5,%6,%7}, {%8,%9}, {%0,%1,%2,%3};" \
                 : "+f"((d)[0]), "+f"((d)[1]), "+f"((d)[2]), "+f"((d)[3]) \
                 : "r"((a)[0]), "r"((a)[1]), "r"((a)[2]), "r"((a)[3]), "r"((b)[0]), "r"((b)[1]))
#define CP_ASYNC16(dst, src) \
    asm volatile("cp.async.cg.shared.global [%0], [%1], 16;" \
                 :: "r"((uint32_t)(dst)), "l"((size_t)__cvta_generic_to_global(src)) : "memory")
#define CP_COMMIT() asm volatile("cp.async.commit_group;" ::: "memory")
#define CP_WAIT(n)  asm volatile("cp.async.wait_group %0;" :: "n"(n) : "memory")

// ---- prep: split codebook + bias -------------------------------------------
__global__ void prep_kernel(const float* __restrict__ W) {
    int k = blockIdx.x * blockDim.x + threadIdx.x;
    if (k >= NCODE) return;
    float s = 0.0f;
#pragma unroll
    for (int d = 0; d < DIM; d++) {
        float v = W[(size_t)k * DIM + d];
        __nv_bfloat16 h, m, l;
        split3(v, h, m, l);
        g_Wsplit[0][k][d] = h; g_Wsplit[1][k][d] = m; g_Wsplit[2][k][d] = l;
        s = fmaf(v, v, s);
    }
    g_bias[k] = -0.5f * s;
}

// issue cp.async for B chunk `kbase` into buffer bsel
__device__ __forceinline__ void prefetch_chunk(uint32_t sbase, int bsel, int kbase, int tid) {
    const char* gw = reinterpret_cast<const char*>(g_Wsplit);
#pragma unroll
    for (int t = 0; t < 6; t++) {
        int i = tid + t * THREADS;                 // 0..1535
        int split = i >> 9, rem = i & 511, n = rem >> 3, ch = rem & 7;
        uint32_t dst = sbase + SM_B + bsel * BUF_B + split * SPLIT_B + n * ROWB + ch * 16;
        const char* src = gw + (((size_t)split * NCODE + kbase + n) * 8 + ch) * 16;
        CP_ASYNC16(dst, src);
    }
    if (tid < 16)
        CP_ASYNC16(sbase + SM_BIAS + bsel * 256 + tid * 16,
                   reinterpret_cast<const char*>(g_bias) + (size_t)kbase * 4 + tid * 16);
    CP_COMMIT();
}

// ---- main kernel ------------------------------------------------------------
__global__ __launch_bounds__(THREADS, 2)
void vq_kernel(const float* __restrict__ x,
               const float* __restrict__ W,
               float* __restrict__ out) {
    extern __shared__ char smem[];
    const uint32_t sbase = smem_to_u32(smem);
    const int tid  = threadIdx.x;
    const int lane = tid & 31;
    const int wid  = tid >> 5;
    const int wm   = wid * 16;          // 16 rows per warp, all 64 codes/chunk

    // kick off chunk 0 load before anything else
    prefetch_chunk(sbase, 0, 0, tid);

    // ---- stage A rows into smem (3-way split) -------------
    {
        const int row = tid >> 1, half = tid & 1;
        const float4* xr = reinterpret_cast<const float4*>(
            x + ((size_t)blockIdx.x * MCTA + row) * DIM + half * 32);
        char* a0 = smem + SM_A + row * ROWB + half * 64;
#pragma unroll
        for (int i = 0; i < 8; i++) {
            float4 v = xr[i];
            __nv_bfloat16 h0, m0, l0, h1, m1, l1, h2, m2, l2, h3, m3, l3;
            split3(v.x, h0, m0, l0); split3(v.y, h1, m1, l1);
            split3(v.z, h2, m2, l2); split3(v.w, h3, m3, l3);
            *reinterpret_cast<uint32_t*>(a0 + 0 * SPLIT_A + i * 8)     = pack2(h0, h1);
            *reinterpret_cast<uint32_t*>(a0 + 0 * SPLIT_A + i * 8 + 4) = pack2(h2, h3);
            *reinterpret_cast<uint32_t*>(a0 + 1 * SPLIT_A + i * 8)     = pack2(m0, m1);
            *reinterpret_cast<uint32_t*>(a0 + 1 * SPLIT_A + i * 8 + 4) = pack2(m2, m3);
            *reinterpret_cast<uint32_t*>(a0 + 2 * SPLIT_A + i * 8)     = pack2(l0, l1);
            *reinterpret_cast<uint32_t*>(a0 + 2 * SPLIT_A + i * 8 + 4) = pack2(l2, l3);
        }
    }
    __syncthreads();

    // ---- A fragments -> registers, persistent for all chunks ----
    uint32_t Af[3][4][4];
    {
        const uint32_t aB = sbase + SM_A + (uint32_t)(wm + (lane & 15)) * ROWB + (lane >> 4) * 16;
#pragma unroll
        for (int sa = 0; sa < 3; sa++)
#pragma unroll
            for (int k = 0; k < 4; k++)
                LDSM_X4(Af[sa][k][0], Af[sa][k][1], Af[sa][k][2], Af[sa][k][3],
                        aB + sa * SPLIT_A + k * 32);
    }

    float best[2] = {-3.0e38f, -3.0e38f};
    int   bidx[2] = {0, 0};

    // B ldmatrix base: x4 covers two n-tiles (codes n0..n0+7 and n0+8..n0+15)
    const uint32_t bb = sbase + SM_B
        + (uint32_t)(((lane >> 4) & 1) * 8 + (lane & 7)) * ROWB
        + ((lane >> 3) & 1) * 16;

    for (int c = 0; c < NCHUNKS; c++) {
        if (c + 1 < NCHUNKS) {
            prefetch_chunk(sbase, (c + 1) & 1, (c + 1) * NCHUNK, tid);
            CP_WAIT(1);
        } else {
            CP_WAIT(0);
        }
        __syncthreads();

        const float* sBias = reinterpret_cast<const float*>(smem + SM_BIAS + (c & 1) * 256);
        float acc[8][4];
#pragma unroll
        for (int nt = 0; nt < 8; nt++) {
            float2 b01 = *reinterpret_cast<const float2*>(&sBias[nt * 8 + (lane & 3) * 2]);
            acc[nt][0] = b01.x; acc[nt][1] = b01.y;
            acc[nt][2] = b01.x; acc[nt][3] = b01.y;
        }

        const uint32_t bbc = bb + (c & 1) * BUF_B;
#pragma unroll
        for (int k = 0; k < 4; k++) {
#pragma unroll
            for (int sb = 0; sb < 3; sb++) {
#pragma unroll
                for (int np = 0; np < 2; np++) {   // pairs of 16-wide n-tiles
                    uint32_t Bf0[4], Bf1[4];
                    uint32_t bB = bbc + sb * SPLIT_B + np * 32 * ROWB + k * 32;
                    LDSM_X4(Bf0[0], Bf0[1], Bf0[2], Bf0[3], bB);
                    LDSM_X4(Bf1[0], Bf1[1], Bf1[2], Bf1[3], bB + 16 * ROWB);
                    // 4 independent acc chains per sa step (dep distance 4)
#pragma unroll
                    for (int sa = 0; sa < 3 - sb; sa++) {
                        MMA_BF16(acc[4 * np + 0], Af[sa][k], Bf0);
                        MMA_BF16(acc[4 * np + 1], Af[sa][k], Bf0 + 2);
                        MMA_BF16(acc[4 * np + 2], Af[sa][k], Bf1);
                        MMA_BF16(acc[4 * np + 3], Af[sa][k], Bf1 + 2);
                    }
                }
            }
        }

        // argmax update: 2 row-chains per thread (rows lane>>2 and +8)
#pragma unroll
        for (int nt = 0; nt < 8; nt++)
#pragma unroll
            for (int q = 0; q < 2; q++)
#pragma unroll
                for (int e = 0; e < 2; e++) {
                    float v = acc[nt][q * 2 + e];
                    int n = c * NCHUNK + nt * 8 + (lane & 3) * 2 + e;
                    if (v > best[q]) { best[q] = v; bidx[q] = n; }
                }

        __syncthreads();   // buf (c&1) free for the c+2 prefetch
    }

    // ---- reduce across the 4 lanes sharing each row (cols) ----
#pragma unroll
    for (int q = 0; q < 2; q++) {
#pragma unroll
        for (int off = 1; off < 4; off <<= 1) {
            float ov = __shfl_xor_sync(0xFFFFFFFFu, best[q], off);
            int   oi = __shfl_xor_sync(0xFFFFFFFFu, bidx[q], off);
            if (ov > best[q] || (ov == best[q] && oi < bidx[q])) {
                best[q] = ov; bidx[q] = oi;
            }
        }
    }

    // ---- gather codewords + write outputs ----
    const int lq = lane & 3;   // dim slice lq*16 .. lq*16+15
#pragma unroll
    for (int q = 0; q < 2; q++) {
        const int r = wm + (lane >> 2) + q * 8;
        const size_t grow = (size_t)blockIdx.x * MCTA + r;
        const int K = bidx[q];
        const float4* wsrc = reinterpret_cast<const float4*>(W + (size_t)K * DIM + lq * 16);
        float4* o1 = reinterpret_cast<float4*>(out + grow * DIM + lq * 16);
        float4* o2 = reinterpret_cast<float4*>(out + ((size_t)NROWS + grow) * DIM + lq * 16);
#pragma unroll
        for (int i = 0; i < 4; i++) {
            float4 v = wsrc[i];
            o1[i] = v;
            o2[i] = v;
        }
        if (lq == 0)
            out[(size_t)2 * NROWS * DIM + grow] = (float)K;
    }
}

// ---- launch -----------------------------------------------------------------
extern "C" void kernel_launch(void* const* d_in, const int* in_sizes, int n_in,
                              void* d_out, int out_size) {
    const float* x = (const float*)d_in[0];
    const float* W = (const float*)d_in[1];
    float* out = (float*)d_out;

    cudaFuncSetAttribute(vq_kernel, cudaFuncAttributeMaxDynamicSharedMemorySize, SMEM_TOTAL);
    prep_kernel<<<NCODE / 256, 256>>>(W);
    vq_kernel<<<NROWS / MCTA, THREADS, SMEM_TOTAL>>>(x, W, out);
}